// round 4
// baseline (speedup 1.0000x reference)
#include <cuda_runtime.h>

// Problem constants
#define S2       100                  // S*S
#define NCH      24                   // 3*B + C
#define NCLS     21
#define BATCHN   32768
#define NCELLS   (BATCHN * S2)        // 3,276,800
#define TILE     256                  // cells per block tile
#define NTILES   (NCELLS / TILE)      // 12800
#define GRID     3200                 // exactly 4 tiles per block
#define SSTRIDE  257                  // padded smem stride (channel-major)

// Loss weights
#define LAMBDA_COORD 10.0
#define LAMBDA_NOOBJ 1.0
#define LAMBDA_CLASS 0.5

// log(w / SCALE) = log(w * INV_SCALE), SCALE = 6.5131/40
__device__ __constant__ float INV_SCALE = 40.0f / 6.5131f;

// Cross-block accumulators [xy, wh, obj, noobj, class], each on its own
// 128B line so end-of-block atomics hash to distinct LTS partitions.
// Zero-initialized at module load; finalize_kernel resets them after each
// read, so every kernel_launch (and graph replay) starts from zero state.
#define ACC_STRIDE 16   // doubles per accumulator slot (128 B)
__device__ double g_acc[5 * ACC_STRIDE];   // static-init to 0.0

__device__ __forceinline__ float warp_reduce(float v) {
#pragma unroll
    for (int o = 16; o > 0; o >>= 1)
        v += __shfl_down_sync(0xffffffffu, v, o);
    return v;
}

__global__ __launch_bounds__(256)
void loss_kernel(const float4* __restrict__ pred4,   // NCELLS*6 float4
                 const float4* __restrict__ tgt4) {  // NCELLS float4
    // channel-major staging: s[ch*SSTRIDE + cell], ch in [0,24), cell in [0,256)
    __shared__ float s[NCH * SSTRIDE];

    float lxy = 0.f, lwh = 0.f, lobj = 0.f, lnoobj = 0.f, lcls = 0.f;
    const int tid = threadIdx.x;

    for (int tile = blockIdx.x; tile < NTILES; tile += GRID) {
        // ---- coalesced target load (held in registers across syncs) ----
        const float4 t = tgt4[tile * TILE + tid];

        // ---- coalesced pred load -> smem channel-major transpose ----
        const float4* pbase = pred4 + (size_t)tile * (TILE * 6);
#pragma unroll
        for (int k = 0; k < 6; k++) {
            const int f = tid + k * TILE;          // local float4 index
            const float4 v = pbase[f];
            const int c = f / 6;                   // cell within tile
            const int j = f - 6 * c;               // float4 slot in cell
            const int ch = 4 * j;
            s[(ch + 0) * SSTRIDE + c] = v.x;
            s[(ch + 1) * SSTRIDE + c] = v.y;
            s[(ch + 2) * SSTRIDE + c] = v.z;
            s[(ch + 3) * SSTRIDE + c] = v.w;
        }
        __syncthreads();

        // ---- per-cell loss; reads conflict-free (fixed ch, lane = cell) ----
        const float conf_t = t.z;  // 0 or 1
        const float sig_conf = 1.f / (1.f + __expf(-s[2 * SSTRIDE + tid]));

        if (conf_t > 0.f) {
            const float dc = sig_conf - conf_t;
            lobj += dc * dc;

            const float sig_x = 1.f / (1.f + __expf(-s[0 * SSTRIDE + tid]));
            const float dx = sig_x - t.x;
            lxy += dx * dx;

            const float dw = s[1 * SSTRIDE + tid] - __logf(t.y * INV_SCALE);
            lwh += dw * dw;

            if (t.w > 0.f) {
                float esum = 0.f, wsum = 0.f;
#pragma unroll
                for (int c = 0; c < NCLS; c++) {
                    const float e = __expf(s[(3 + c) * SSTRIDE + tid]);
                    esum += e;
                    wsum += e * (1.0f + 0.5f * (float)c);
                }
                const float pred_mass = wsum / esum;
                const float diff = 10.f * (pred_mass + 1.f) / (t.w + 1.f) - 10.f;
                const float ad = fabsf(diff);
                lcls += (ad < 1.f) ? 0.5f * diff * diff : (ad - 0.5f);
            }
        } else {
            lnoobj += sig_conf * sig_conf;   // target conf == 0
        }
        __syncthreads();   // protect smem before next tile's stores
    }

    // ---- block reduction: warp shuffle -> smem -> warp0 -> double atomics ----
    __shared__ float r[5][8];
    const int lane = tid & 31;
    const int wid  = tid >> 5;

    lxy    = warp_reduce(lxy);
    lwh    = warp_reduce(lwh);
    lobj   = warp_reduce(lobj);
    lnoobj = warp_reduce(lnoobj);
    lcls   = warp_reduce(lcls);

    if (lane == 0) {
        r[0][wid] = lxy;  r[1][wid] = lwh;  r[2][wid] = lobj;
        r[3][wid] = lnoobj;  r[4][wid] = lcls;
    }
    __syncthreads();

    if (wid == 0) {
        float a0 = (lane < 8) ? r[0][lane] : 0.f;
        float a1 = (lane < 8) ? r[1][lane] : 0.f;
        float a2 = (lane < 8) ? r[2][lane] : 0.f;
        float a3 = (lane < 8) ? r[3][lane] : 0.f;
        float a4 = (lane < 8) ? r[4][lane] : 0.f;
        a0 = warp_reduce(a0);
        a1 = warp_reduce(a1);
        a2 = warp_reduce(a2);
        a3 = warp_reduce(a3);
        a4 = warp_reduce(a4);
        if (lane == 0) {
            atomicAdd(&g_acc[0 * ACC_STRIDE], (double)a0);
            atomicAdd(&g_acc[1 * ACC_STRIDE], (double)a1);
            atomicAdd(&g_acc[2 * ACC_STRIDE], (double)a2);
            atomicAdd(&g_acc[3 * ACC_STRIDE], (double)a3);
            atomicAdd(&g_acc[4 * ACC_STRIDE], (double)a4);
        }
    }
}

__global__ void finalize_kernel(float* __restrict__ out) {
    if (threadIdx.x == 0 && blockIdx.x == 0) {
        const double xy  = g_acc[0 * ACC_STRIDE];
        const double wh  = g_acc[1 * ACC_STRIDE];
        const double obj = g_acc[2 * ACC_STRIDE];
        const double nob = g_acc[3 * ACC_STRIDE];
        const double cls = g_acc[4 * ACC_STRIDE];
        const double total = LAMBDA_COORD * (xy + wh) + obj
                           + LAMBDA_NOOBJ * nob + LAMBDA_CLASS * cls;
        const double inv_bs = 1.0 / (double)BATCHN;
        out[0] = (float)(xy  * inv_bs);
        out[1] = (float)(wh  * inv_bs);
        out[2] = (float)(obj * inv_bs);
        out[3] = (float)(nob * inv_bs);
        out[4] = (float)(cls * inv_bs);
        out[5] = (float)(total * inv_bs);
        // Reset for the next launch / graph replay (deterministic state).
        g_acc[0 * ACC_STRIDE] = 0.0;
        g_acc[1 * ACC_STRIDE] = 0.0;
        g_acc[2 * ACC_STRIDE] = 0.0;
        g_acc[3 * ACC_STRIDE] = 0.0;
        g_acc[4 * ACC_STRIDE] = 0.0;
    }
}

extern "C" void kernel_launch(void* const* d_in, const int* in_sizes, int n_in,
                              void* d_out, int out_size) {
    // pred is the big input (NCELLS*24 floats); target is NCELLS*4
    const float* pred = (const float*)d_in[0];
    const float* tgt  = (const float*)d_in[1];
    if (n_in >= 2 && in_sizes[0] < in_sizes[1]) {
        pred = (const float*)d_in[1];
        tgt  = (const float*)d_in[0];
    }

    loss_kernel<<<GRID, 256>>>(reinterpret_cast<const float4*>(pred),
                               reinterpret_cast<const float4*>(tgt));
    finalize_kernel<<<1, 32>>>((float*)d_out);
}